// round 10
// baseline (speedup 1.0000x reference)
#include <cuda_runtime.h>
#include <math.h>
#include <stdint.h>

#define DD 256
#define AA 64
#define NROWS 4096   // B*N
#define NCTA 148     // persistent CTAs for attn
#define NBUF 3       // pipeline depth

// ---------------- scratch (device globals; no allocation allowed) ----------
__device__ float g_W2[DD * DD];      // scale * Wq^T @ Wk
__device__ float g_b2[DD];           // scale * bq @ Wk
__device__ float g_u[DD];            // scale * Wq^T @ bk
__device__ float g_c;                // scale * bq . bk
__device__ float g_Qk[NROWS * DD];   // cc @ g_W2 + g_b2
__device__ float g_qb[NROWS];        // cc_row . g_u + g_c
__device__ float g_wsum[NROWS * DD]; // sum_a p[a] * anchor[a,:]
__device__ float g_S[NROWS];         // sum_a p[a]

// ---------------- f32x2 helpers ---------------------------------------------
__device__ __forceinline__ unsigned long long pack2(float x, float y) {
    unsigned long long r;
    asm("mov.b64 %0, {%1, %2};" : "=l"(r) : "f"(x), "f"(y));
    return r;
}
__device__ __forceinline__ void unpack2(unsigned long long v, float& x, float& y) {
    asm("mov.b64 {%0, %1}, %2;" : "=f"(x), "=f"(y) : "l"(v));
}
__device__ __forceinline__ void fma2(unsigned long long& d, unsigned long long a,
                                     unsigned long long b) {
    asm("fma.rn.f32x2 %0, %1, %2, %0;" : "+l"(d) : "l"(a), "l"(b));
}

// ---------------- merged prep: blocks 0-15 -> W2 tiles; 16,17 -> vectors ----
__device__ __forceinline__ void mma_tile4(const float (*As)[68], const float (*Bs)[68],
                                          int ty, int tx, float acc[4][4]) {
#pragma unroll
    for (int kk = 0; kk < 16; ++kk) {
        float4 av = *reinterpret_cast<const float4*>(&As[kk][ty * 4]);
        float4 bv = *reinterpret_cast<const float4*>(&Bs[kk][tx * 4]);
        float ar[4] = {av.x, av.y, av.z, av.w};
        float br[4] = {bv.x, bv.y, bv.z, bv.w};
#pragma unroll
        for (int i = 0; i < 4; ++i)
#pragma unroll
            for (int j = 0; j < 4; ++j)
                acc[i][j] = fmaf(ar[i], br[j], acc[i][j]);
    }
}

__global__ __launch_bounds__(256) void prep_all(const float* __restrict__ Wq,
                                                const float* __restrict__ bq,
                                                const float* __restrict__ Wk,
                                                const float* __restrict__ bk) {
    const float scale = 0.0625f;  // 1/sqrt(256)
    const int blk = blockIdx.x;
    const int t = threadIdx.x;
    if (blk >= 16) {
        if (blk == 16) {
            float s = 0.f;
            for (int k = 0; k < DD; ++k) s = fmaf(Wq[k * DD + t], bk[k], s);
            g_u[t] = scale * s;
            if (t == 0) {
                float c = 0.f;
                for (int k = 0; k < DD; ++k) c = fmaf(bq[k], bk[k], c);
                g_c = scale * c;
            }
        } else {
            float s = 0.f;
            for (int k = 0; k < DD; ++k) s = fmaf(bq[k], Wk[k * DD + t], s);
            g_b2[t] = scale * s;
        }
        return;
    }
    __shared__ float As[16][68];
    __shared__ float Bs[16][68];
    int tx = t % 16, ty = t / 16;
    int d0 = (blk % 4) * 64, e0 = (blk / 4) * 64;
    float acc[4][4] = {};
    for (int k0 = 0; k0 < DD; k0 += 16) {
        float4 a = *reinterpret_cast<const float4*>(Wq + (k0 + ty) * DD + d0 + tx * 4);
        float4 b = *reinterpret_cast<const float4*>(Wk + (k0 + ty) * DD + e0 + tx * 4);
        *reinterpret_cast<float4*>(&As[ty][tx * 4]) = a;
        *reinterpret_cast<float4*>(&Bs[ty][tx * 4]) = b;
        __syncthreads();
        mma_tile4(As, Bs, ty, tx, acc);
        __syncthreads();
    }
#pragma unroll
    for (int i = 0; i < 4; ++i)
#pragma unroll
        for (int j = 0; j < 4; ++j)
            g_W2[(d0 + ty * 4 + i) * DD + e0 + tx * 4 + j] = scale * acc[i][j];
}

// ---------------- gemm_v3: C[4096,256] = A @ B (+bias), 128x64 tile ---------
// microtile 4m x 8n, acc = f32x2 n-pairs (B read as natural ull, A dup-packed)
// BMODE 0: A = Ap (cc), B = g_W2 [K,N] row-major, C = g_Qk, bias = g_b2[n];
//          blockIdx.y==0 also computes g_qb[m]
// BMODE 1: A = g_wsum, B = Bp (Wv [N,K], transposed on stage), C = Cp,
//          bias = biasp[n] * g_S[m]
template <int BMODE>
__global__ __launch_bounds__(256) void gemm_v3(const float* __restrict__ Ap,
                                               const float* __restrict__ Bp,
                                               const float* __restrict__ biasp,
                                               float* __restrict__ Cp) {
    __shared__ float As[2][16][132];  // [k][m: 128 + pad]
    __shared__ float Bs[2][16][68];   // [k][n: 64 + pad]
    __shared__ float s_u[DD];

    const float* A = (BMODE == 0) ? Ap : g_wsum;
    const float* B = (BMODE == 0) ? g_W2 : Bp;
    const float* bias = (BMODE == 0) ? g_b2 : biasp;
    float* C = (BMODE == 0) ? g_Qk : Cp;

    const int t = threadIdx.x;
    const int tx = t & 7, ty = t >> 3;           // compute map: 32 m-grp x 8 n-grp
    const int m0 = blockIdx.x * 128, n0 = blockIdx.y * 64;
    const int lmA = t >> 1, kA = (t & 1) * 8;    // A staging: 128 rows x 2 k-grp
    const int kB = t >> 4, nB = (t & 15) * 4;    // B staging (BMODE 0)
    const int nW = t >> 2, kW = (t & 3) * 4;     // B staging (BMODE 1)
    const bool qb_active = (BMODE == 0) && (blockIdx.y == 0);

    if (qb_active) s_u[t] = g_u[t];

    float qb_part = 0.f;

    float4 a0, a1, b0;
    a0 = *reinterpret_cast<const float4*>(A + (size_t)(m0 + lmA) * DD + kA);
    a1 = *reinterpret_cast<const float4*>(A + (size_t)(m0 + lmA) * DD + kA + 4);
    if (BMODE == 0)
        b0 = *reinterpret_cast<const float4*>(B + kB * DD + n0 + nB);
    else
        b0 = *reinterpret_cast<const float4*>(B + (size_t)(n0 + nW) * DD + kW);
    {
        float av[8] = {a0.x, a0.y, a0.z, a0.w, a1.x, a1.y, a1.z, a1.w};
#pragma unroll
        for (int c = 0; c < 8; ++c) As[0][kA + c][lmA] = av[c];
        if (qb_active) {
#pragma unroll
            for (int c = 0; c < 8; ++c)
                qb_part = fmaf(av[c], s_u[kA + c], qb_part);
        }
        if (BMODE == 0) {
            *reinterpret_cast<float4*>(&Bs[0][kB][nB]) = b0;
        } else {
            float bvv[4] = {b0.x, b0.y, b0.z, b0.w};
#pragma unroll
            for (int c = 0; c < 4; ++c) Bs[0][kW + c][nW] = bvv[c];
        }
    }
    __syncthreads();

    unsigned long long acc[4][4];
#pragma unroll
    for (int i = 0; i < 4; ++i)
#pragma unroll
        for (int j = 0; j < 4; ++j) acc[i][j] = pack2(0.f, 0.f);

    for (int c = 0; c < 16; ++c) {
        const int buf = c & 1;
        if (c + 1 < 16) {
            const int k0 = (c + 1) * 16;
            a0 = *reinterpret_cast<const float4*>(A + (size_t)(m0 + lmA) * DD + k0 + kA);
            a1 = *reinterpret_cast<const float4*>(A + (size_t)(m0 + lmA) * DD + k0 + kA + 4);
            if (BMODE == 0)
                b0 = *reinterpret_cast<const float4*>(B + (k0 + kB) * DD + n0 + nB);
            else
                b0 = *reinterpret_cast<const float4*>(B + (size_t)(n0 + nW) * DD + k0 + kW);
        }
#pragma unroll
        for (int kk = 0; kk < 16; ++kk) {
            float4 af = *reinterpret_cast<const float4*>(&As[buf][kk][ty * 4]);
            ulonglong2 b01 = *reinterpret_cast<const ulonglong2*>(&Bs[buf][kk][tx * 4]);
            ulonglong2 b23 =
                *reinterpret_cast<const ulonglong2*>(&Bs[buf][kk][32 + tx * 4]);
            unsigned long long a2[4] = {pack2(af.x, af.x), pack2(af.y, af.y),
                                        pack2(af.z, af.z), pack2(af.w, af.w)};
            unsigned long long bb[4] = {b01.x, b01.y, b23.x, b23.y};
#pragma unroll
            for (int i = 0; i < 4; ++i) {
                fma2(acc[i][0], a2[i], bb[0]);
                fma2(acc[i][1], a2[i], bb[1]);
                fma2(acc[i][2], a2[i], bb[2]);
                fma2(acc[i][3], a2[i], bb[3]);
            }
        }
        if (c + 1 < 16) {
            const int k0 = (c + 1) * 16;
            float av[8] = {a0.x, a0.y, a0.z, a0.w, a1.x, a1.y, a1.z, a1.w};
#pragma unroll
            for (int c2 = 0; c2 < 8; ++c2) As[buf ^ 1][kA + c2][lmA] = av[c2];
            if (qb_active) {
#pragma unroll
                for (int c2 = 0; c2 < 8; ++c2)
                    qb_part = fmaf(av[c2], s_u[k0 + kA + c2], qb_part);
            }
            if (BMODE == 0) {
                *reinterpret_cast<float4*>(&Bs[buf ^ 1][kB][nB]) = b0;
            } else {
                float bvv[4] = {b0.x, b0.y, b0.z, b0.w};
#pragma unroll
                for (int c2 = 0; c2 < 4; ++c2) Bs[buf ^ 1][kW + c2][nW] = bvv[c2];
            }
        }
        __syncthreads();
    }

    if (qb_active) {
        float p = qb_part + __shfl_down_sync(0xffffffffu, qb_part, 1);
        if ((t & 1) == 0) g_qb[m0 + lmA] = p + g_c;
    }

    float4 bb0 = *reinterpret_cast<const float4*>(bias + n0 + tx * 4);
    float4 bb1 = *reinterpret_cast<const float4*>(bias + n0 + 32 + tx * 4);
#pragma unroll
    for (int i = 0; i < 4; ++i) {
        const int m = m0 + ty * 4 + i;
        float f0, f1, f2, f3, f4, f5, f6, f7;
        unpack2(acc[i][0], f0, f1);
        unpack2(acc[i][1], f2, f3);
        unpack2(acc[i][2], f4, f5);
        unpack2(acc[i][3], f6, f7);
        float4 o0, o1;
        if (BMODE == 1) {
            float s = g_S[m];
            o0 = make_float4(f0 + bb0.x * s, f1 + bb0.y * s, f2 + bb0.z * s,
                             f3 + bb0.w * s);
            o1 = make_float4(f4 + bb1.x * s, f5 + bb1.y * s, f6 + bb1.z * s,
                             f7 + bb1.w * s);
        } else {
            o0 = make_float4(f0 + bb0.x, f1 + bb0.y, f2 + bb0.z, f3 + bb0.w);
            o1 = make_float4(f4 + bb1.x, f5 + bb1.y, f6 + bb1.z, f7 + bb1.w);
        }
        *reinterpret_cast<float4*>(C + (size_t)m * DD + n0 + tx * 4) = o0;
        *reinterpret_cast<float4*>(C + (size_t)m * DD + n0 + 32 + tx * 4) = o1;
    }
}

// ---------------- attn v7: two independent 256-thread halves per CTA --------
__global__ __launch_bounds__(512) void attn_v7(const float* __restrict__ anchor,
                                               const float* __restrict__ sims) {
    extern __shared__ float sm[];
    float* sP = sm + NBUF * AA * DD;  // [2 halves][8 warps][256]
    __shared__ float s_adj[2][AA];
    __shared__ __align__(8) unsigned long long mbar[NBUF];

    const int t = threadIdx.x;
    const int half = t >> 8;
    const int th = t & 255;
    const int w = th >> 5;
    const int lane = t & 31;
    const int cta = blockIdx.x;
    const int iters = (NROWS - cta + NCTA - 1) / NCTA;

    uint32_t mb_base, sA_base;
    asm("{ .reg .u64 x; cvta.to.shared.u64 x, %1; cvt.u32.u64 %0, x; }"
        : "=r"(mb_base) : "l"(mbar));
    asm("{ .reg .u64 x; cvta.to.shared.u64 x, %1; cvt.u32.u64 %0, x; }"
        : "=r"(sA_base) : "l"(sm));

    if (t == 0) {
#pragma unroll
        for (int j = 0; j < NBUF; ++j)
            asm volatile("mbarrier.init.shared::cta.b64 [%0], 1;"
                         :: "r"(mb_base + j * 8));
    }
    __syncthreads();
    if (t == 0) {
#pragma unroll
        for (int j = 0; j < NBUF; ++j)
            if (j < iters) {
                uint32_t mb = mb_base + j * 8;
                asm volatile("mbarrier.arrive.expect_tx.shared::cta.b64 _, [%0], %1;"
                             :: "r"(mb), "r"(65536));
                asm volatile(
                    "cp.async.bulk.shared::cta.global.mbarrier::complete_tx::bytes "
                    "[%0], [%1], %2, [%3];"
                    :: "r"(sA_base + j * 65536),
                       "l"(anchor + (size_t)(cta + j * NCTA) * AA * DD),
                       "r"(65536), "r"(mb) : "memory");
            }
    }
    __syncthreads();

    const int bar_id = 1 + half;

    for (int it = half; it < iters; it += 2) {
        const int row = cta + it * NCTA;
        const int b = it % NBUF;
        const float* sA = sm + b * AA * DD;

        const float4* qg = reinterpret_cast<const float4*>(g_Qk + (size_t)row * DD);
        float4 q0 = qg[lane], q1 = qg[lane + 32];
        float qb = g_qb[row];
        float simv = (lane < 8) ? sims[row * AA + w + 8 * lane] : 0.f;

        {
            uint32_t mb = mb_base + b * 8;
            int par = (it / NBUF) & 1;
            asm volatile(
                "{ .reg .pred P;\n"
                "WL%=: mbarrier.try_wait.parity.acquire.cta.shared::cta.b64 P, [%0], %1;\n"
                "@!P bra WL%=; }"
                :: "r"(mb), "r"(par) : "memory");
        }

        float4 x0[8], x1[8];
        float val = 0.f;
#pragma unroll
        for (int j = 0; j < 8; ++j) {
            const int a = w + 8 * j;
            const float4* a4 = reinterpret_cast<const float4*>(sA + a * DD);
            x0[j] = a4[lane];
            x1[j] = a4[lane + 32];
            float s = q0.x * x0[j].x + q0.y * x0[j].y + q0.z * x0[j].z +
                      q0.w * x0[j].w + q1.x * x1[j].x + q1.y * x1[j].y +
                      q1.z * x1[j].z + q1.w * x1[j].w;
#pragma unroll
            for (int o = 16; o; o >>= 1) s += __shfl_xor_sync(0xffffffffu, s, o);
            if (lane == j) val = s + qb + simv;
        }
        if (lane < 8) s_adj[half][w + 8 * lane] = val;

        asm volatile("bar.sync %0, 256;" :: "r"(bar_id) : "memory");

        if (th == 0 && it + NBUF < iters) {
            uint32_t mb = mb_base + b * 8;
            asm volatile("mbarrier.arrive.expect_tx.shared::cta.b64 _, [%0], %1;"
                         :: "r"(mb), "r"(65536));
            asm volatile(
                "cp.async.bulk.shared::cta.global.mbarrier::complete_tx::bytes "
                "[%0], [%1], %2, [%3];"
                :: "r"(sA_base + b * 65536),
                   "l"(anchor + (size_t)(row + NBUF * NCTA) * AA * DD),
                   "r"(65536), "r"(mb) : "memory");
        }

        float p0, p1;
        {
            float v0 = s_adj[half][lane], v1 = s_adj[half][lane + 32];
            float sum = v0 + v1;
            float mx = fmaxf(v0, v1);
#pragma unroll
            for (int o = 16; o; o >>= 1) {
                sum += __shfl_xor_sync(0xffffffffu, sum, o);
                mx = fmaxf(mx, __shfl_xor_sync(0xffffffffu, mx, o));
            }
            if (sum != 0.0f) {
                float e0 = __expf(v0 - mx), e1 = __expf(v1 - mx);
                float es = e0 + e1;
#pragma unroll
                for (int o = 16; o; o >>= 1) es += __shfl_xor_sync(0xffffffffu, es, o);
                float inv = 1.0f / es;
                p0 = e0 * inv;
                p1 = e1 * inv;
                if (th == 0) g_S[row] = 1.0f;
            } else {
                p0 = v0;
                p1 = v1;
                if (th == 0) g_S[row] = 0.0f;
            }
        }
        float pa[8];
#pragma unroll
        for (int j = 0; j < 4; ++j)
            pa[j] = __shfl_sync(0xffffffffu, p0, w + 8 * j);
#pragma unroll
        for (int j = 4; j < 8; ++j)
            pa[j] = __shfl_sync(0xffffffffu, p1, w + 8 * j - 32);

        float4 acc0 = make_float4(0.f, 0.f, 0.f, 0.f);
        float4 acc1 = make_float4(0.f, 0.f, 0.f, 0.f);
#pragma unroll
        for (int j = 0; j < 8; ++j) {
            acc0.x = fmaf(pa[j], x0[j].x, acc0.x);
            acc0.y = fmaf(pa[j], x0[j].y, acc0.y);
            acc0.z = fmaf(pa[j], x0[j].z, acc0.z);
            acc0.w = fmaf(pa[j], x0[j].w, acc0.w);
            acc1.x = fmaf(pa[j], x1[j].x, acc1.x);
            acc1.y = fmaf(pa[j], x1[j].y, acc1.y);
            acc1.z = fmaf(pa[j], x1[j].z, acc1.z);
            acc1.w = fmaf(pa[j], x1[j].w, acc1.w);
        }
        float* myP = sP + (half * 8 + w) * DD;
        *reinterpret_cast<float4*>(myP + lane * 4) = acc0;
        *reinterpret_cast<float4*>(myP + 128 + lane * 4) = acc1;

        asm volatile("bar.sync %0, 256;" :: "r"(bar_id) : "memory");

        {
            const float* hp = sP + half * 8 * DD;
            float a = 0.f;
#pragma unroll
            for (int i = 0; i < 8; ++i) a += hp[i * DD + th];
            g_wsum[(size_t)row * DD + th] = a;
        }
    }
}

// ---------------- launch ----------------------------------------------------
extern "C" void kernel_launch(void* const* d_in, const int* in_sizes, int n_in,
                              void* d_out, int out_size) {
    const float* cc     = (const float*)d_in[0];
    const float* anchor = (const float*)d_in[1];
    const float* sims   = (const float*)d_in[2];
    const float* Wq     = (const float*)d_in[3];
    const float* bq     = (const float*)d_in[4];
    const float* Wk     = (const float*)d_in[5];
    const float* bk     = (const float*)d_in[6];
    const float* Wv     = (const float*)d_in[7];
    const float* bv     = (const float*)d_in[8];
    float* out = (float*)d_out;

    const int smem_attn = (NBUF * AA * DD + 16 * DD) * (int)sizeof(float);  // 208 KB
    cudaFuncSetAttribute(attn_v7, cudaFuncAttributeMaxDynamicSharedMemorySize,
                         smem_attn);

    prep_all<<<18, 256>>>(Wq, bq, Wk, bk);
    gemm_v3<0><<<dim3(32, 4), 256>>>(cc, nullptr, nullptr, nullptr);
    attn_v7<<<NCTA, 512, smem_attn>>>(anchor, sims);
    gemm_v3<1><<<dim3(32, 4), 256>>>(nullptr, Wv, bv, out);
}